// round 1
// baseline (speedup 1.0000x reference)
#include <cuda_runtime.h>
#include <cuda_bf16.h>
#include <math.h>

// ---------------- problem constants ----------------
#define BB 4
#define NN 2048
#define MV 576
#define CC 512
#define HH 8
#define KVH 2
#define DD 64
#define EE 8
#define TOPK 2
#define FF 2048
#define TOK (BB*NN)          // 8192 text tokens
#define KVDIM (KVH*DD)       // 128
#define EROWS 8192           // max assignments per expert (each token picks distinct experts)

// ---------------- static scratch ----------------
__device__ float g_h  [(size_t)TOK*CC];
__device__ float g_q  [(size_t)TOK*CC];
__device__ float g_k  [(size_t)TOK*KVDIM];
__device__ float g_v  [(size_t)TOK*KVDIM];
__device__ float g_att[(size_t)TOK*CC];
__device__ float g_x1 [(size_t)TOK*CC];
__device__ float g_x2 [(size_t)TOK*CC];
__device__ float g_mid[(size_t)EE*EROWS*FF];   // 536 MB
__device__ float g_eo [(size_t)EE*EROWS*CC];   // 134 MB
__device__ int   g_count[EE];
__device__ float g_Psum[EE];
__device__ int   g_tokrow [TOK*TOPK];
__device__ float g_tokgate[TOK*TOPK];
__device__ int   g_tok_of_row[EE*EROWS];

// ---------------- LayerNorm: one block per row ----------------
__global__ void ln_kernel(const float* __restrict__ x, const float* __restrict__ g,
                          const float* __restrict__ b, float* __restrict__ o) {
    int t = blockIdx.x;
    int tid = threadIdx.x;                 // 256 threads, C=512
    const float* xr = x + (size_t)t * CC;
    float v0 = xr[tid], v1 = xr[tid + 256];
    __shared__ float red[256];
    red[tid] = v0 + v1; __syncthreads();
    for (int off = 128; off > 0; off >>= 1) {
        if (tid < off) red[tid] += red[tid + off];
        __syncthreads();
    }
    float mu = red[0] * (1.0f / CC);
    __syncthreads();
    float d0 = v0 - mu, d1 = v1 - mu;
    red[tid] = d0 * d0 + d1 * d1; __syncthreads();
    for (int off = 128; off > 0; off >>= 1) {
        if (tid < off) red[tid] += red[tid + off];
        __syncthreads();
    }
    float rstd = rsqrtf(red[0] * (1.0f / CC) + 1e-6f);
    float* orow = o + (size_t)t * CC;
    orow[tid]       = d0 * rstd * g[tid]       + b[tid];
    orow[tid + 256] = d1 * rstd * g[tid + 256] + b[tid + 256];
}

// ---------------- generic tiled SGEMM: out = A[M,K] @ W[K,N] + bias (+ resid) ----------------
#define BM 64
#define BN 64
#define BK 16
__global__ void gemm_kernel(const float* __restrict__ A, const float* __restrict__ W,
                            const float* __restrict__ bias, const float* __restrict__ resid,
                            float* __restrict__ out, int Mr, int Nc, int Kd) {
    __shared__ float As[BK][BM];
    __shared__ float Bs[BK][BN];
    int tid = threadIdx.x;                 // 256
    int tx = tid & 15, ty = tid >> 4;
    int row0 = blockIdx.y * BM;
    int col0 = blockIdx.x * BN;
    float acc[4][4] = {};
    for (int k0 = 0; k0 < Kd; k0 += BK) {
        #pragma unroll
        for (int i = 0; i < 4; i++) {
            int idx = tid + 256 * i;
            int r = idx >> 4, c = idx & 15;
            int gr = row0 + r;
            As[c][r] = (gr < Mr) ? A[(size_t)gr * Kd + k0 + c] : 0.0f;
        }
        #pragma unroll
        for (int i = 0; i < 4; i++) {
            int idx = tid + 256 * i;
            int r = idx >> 6, c = idx & 63;
            Bs[r][c] = W[(size_t)(k0 + r) * Nc + col0 + c];
        }
        __syncthreads();
        #pragma unroll
        for (int kk = 0; kk < BK; kk++) {
            float4 a4 = reinterpret_cast<const float4*>(&As[kk][0])[ty];
            float4 b4 = reinterpret_cast<const float4*>(&Bs[kk][0])[tx];
            float a[4] = {a4.x, a4.y, a4.z, a4.w};
            float bb[4] = {b4.x, b4.y, b4.z, b4.w};
            #pragma unroll
            for (int i = 0; i < 4; i++)
                #pragma unroll
                for (int j = 0; j < 4; j++)
                    acc[i][j] += a[i] * bb[j];
        }
        __syncthreads();
    }
    #pragma unroll
    for (int i = 0; i < 4; i++) {
        int r = row0 + ty * 4 + i;
        if (r >= Mr) continue;
        #pragma unroll
        for (int j = 0; j < 4; j++) {
            int c = col0 + tx * 4 + j;
            if (c >= Nc) continue;
            float v = acc[i][j];
            if (bias)  v += bias[c];
            if (resid) v += resid[(size_t)r * Nc + c];
            out[(size_t)r * Nc + c] = v;
        }
    }
}

// ---------------- attention: one block per (q, head, batch) ----------------
__global__ void attn_kernel(const float* __restrict__ Q, const float* __restrict__ K,
                            const float* __restrict__ V, float* __restrict__ out,
                            int n_kv, int causal) {
    int qi = blockIdx.x, h = blockIdx.y, b = blockIdx.z;
    int g = h >> 2;                            // H/KVH = 4
    __shared__ float s_q[DD];
    __shared__ float s_sc[2048];
    __shared__ float s_red[128];
    int tid = threadIdx.x;                     // 128
    if (tid < DD) s_q[tid] = Q[((size_t)(b * NN + qi)) * CC + h * DD + tid];
    __syncthreads();
    int nk = causal ? (qi + 1) : n_kv;
    float lmax = -1e30f;
    for (int j = tid; j < nk; j += 128) {
        const float* kr = K + ((size_t)(b * n_kv + j)) * KVDIM + g * DD;
        float s0 = 0, s1 = 0, s2 = 0, s3 = 0;
        #pragma unroll
        for (int d = 0; d < DD; d += 4) {
            s0 += s_q[d]     * kr[d];
            s1 += s_q[d + 1] * kr[d + 1];
            s2 += s_q[d + 2] * kr[d + 2];
            s3 += s_q[d + 3] * kr[d + 3];
        }
        float s = (s0 + s1 + s2 + s3) * 0.125f;  // D^-0.5
        s_sc[j] = s;
        lmax = fmaxf(lmax, s);
    }
    s_red[tid] = lmax; __syncthreads();
    for (int off = 64; off > 0; off >>= 1) {
        if (tid < off) s_red[tid] = fmaxf(s_red[tid], s_red[tid + off]);
        __syncthreads();
    }
    float mx = s_red[0];
    __syncthreads();
    float lsum = 0.0f;
    for (int j = tid; j < nk; j += 128) {
        float e = __expf(s_sc[j] - mx);
        s_sc[j] = e;
        lsum += e;
    }
    s_red[tid] = lsum; __syncthreads();
    for (int off = 64; off > 0; off >>= 1) {
        if (tid < off) s_red[tid] += s_red[tid + off];
        __syncthreads();
    }
    float inv = 1.0f / s_red[0];
    __syncthreads();
    int d = tid & 63, par = tid >> 6;
    float acc = 0.0f;
    for (int j = par; j < nk; j += 2)
        acc += s_sc[j] * V[((size_t)(b * n_kv + j)) * KVDIM + g * DD + d];
    s_red[tid] = acc; __syncthreads();
    if (par == 0) {
        float o = (s_red[d] + s_red[64 + d]) * inv;
        out[((size_t)(b * NN + qi)) * CC + h * DD + d] = o;
    }
}

// ---------------- MoE routing ----------------
__global__ void zero_kernel() {
    int t = threadIdx.x;
    if (t < EE) { g_count[t] = 0; g_Psum[t] = 0.0f; }
}

__global__ void router_kernel(const float* __restrict__ rw, const float* __restrict__ rb) {
    __shared__ float sP[EE];
    int tid = threadIdx.x;
    if (tid < EE) sP[tid] = 0.0f;
    __syncthreads();
    int t = blockIdx.x * blockDim.x + tid;     // 8192 tokens
    float logit[EE];
    const float* hrow = g_h + (size_t)t * CC;
    #pragma unroll
    for (int e = 0; e < EE; e++) logit[e] = rb[e];
    for (int k = 0; k < CC; k++) {
        float hv = hrow[k];
        const float* wr = rw + k * EE;
        #pragma unroll
        for (int e = 0; e < EE; e++) logit[e] += hv * wr[e];
    }
    float mx = logit[0];
    #pragma unroll
    for (int e = 1; e < EE; e++) mx = fmaxf(mx, logit[e]);
    float p[EE], ps = 0.0f;
    #pragma unroll
    for (int e = 0; e < EE; e++) { p[e] = __expf(logit[e] - mx); ps += p[e]; }
    float invs = 1.0f / ps;
    #pragma unroll
    for (int e = 0; e < EE; e++) p[e] *= invs;
    // top-2 (first occurrence wins ties, matching lax.top_k)
    int i0 = 0;
    #pragma unroll
    for (int e = 1; e < EE; e++) if (p[e] > p[i0]) i0 = e;
    int i1 = (i0 == 0) ? 1 : 0;
    #pragma unroll
    for (int e = 0; e < EE; e++) if (e != i0 && p[e] > p[i1]) i1 = e;
    float gs = p[i0] + p[i1];
    float g0 = p[i0] / gs, g1 = p[i1] / gs;
    int s0 = atomicAdd(&g_count[i0], 1);
    int s1 = atomicAdd(&g_count[i1], 1);
    int r0 = i0 * EROWS + s0, r1 = i1 * EROWS + s1;
    g_tok_of_row[r0] = t; g_tok_of_row[r1] = t;
    g_tokrow[t * 2] = r0; g_tokrow[t * 2 + 1] = r1;
    g_tokgate[t * 2] = g0; g_tokgate[t * 2 + 1] = g1;
    #pragma unroll
    for (int e = 0; e < EE; e++) atomicAdd(&sP[e], p[e]);
    __syncthreads();
    if (tid < EE) atomicAdd(&g_Psum[tid], sP[tid]);
}

// ---------------- expert GEMM 1: gathered A, GELU epilogue ----------------
__global__ void egemm1_kernel(const float* __restrict__ ew1, const float* __restrict__ eb1) {
    int e = blockIdx.z;
    int cnt = g_count[e];
    int row0 = blockIdx.y * BM;
    if (row0 >= cnt) return;
    int col0 = blockIdx.x * BN;
    __shared__ float As[BK][BM];
    __shared__ float Bs[BK][BN];
    __shared__ int s_tok[BM];
    int tid = threadIdx.x;
    if (tid < BM) {
        int gr = row0 + tid;
        s_tok[tid] = (gr < cnt) ? g_tok_of_row[e * EROWS + gr] : -1;
    }
    __syncthreads();
    int tx = tid & 15, ty = tid >> 4;
    const float* W = ew1 + (size_t)e * CC * FF;   // [C,F]
    float acc[4][4] = {};
    for (int k0 = 0; k0 < CC; k0 += BK) {
        #pragma unroll
        for (int i = 0; i < 4; i++) {
            int idx = tid + 256 * i;
            int r = idx >> 4, c = idx & 15;
            int tok = s_tok[r];
            As[c][r] = (tok >= 0) ? g_h[(size_t)tok * CC + k0 + c] : 0.0f;
        }
        #pragma unroll
        for (int i = 0; i < 4; i++) {
            int idx = tid + 256 * i;
            int r = idx >> 6, c = idx & 63;
            Bs[r][c] = W[(size_t)(k0 + r) * FF + col0 + c];
        }
        __syncthreads();
        #pragma unroll
        for (int kk = 0; kk < BK; kk++) {
            float4 a4 = reinterpret_cast<const float4*>(&As[kk][0])[ty];
            float4 b4 = reinterpret_cast<const float4*>(&Bs[kk][0])[tx];
            float a[4] = {a4.x, a4.y, a4.z, a4.w};
            float bb[4] = {b4.x, b4.y, b4.z, b4.w};
            #pragma unroll
            for (int i = 0; i < 4; i++)
                #pragma unroll
                for (int j = 0; j < 4; j++)
                    acc[i][j] += a[i] * bb[j];
        }
        __syncthreads();
    }
    #pragma unroll
    for (int i = 0; i < 4; i++) {
        int r = row0 + ty * 4 + i;
        if (r >= cnt) continue;
        #pragma unroll
        for (int j = 0; j < 4; j++) {
            int c = col0 + tx * 4 + j;
            float x = acc[i][j] + eb1[e * FF + c];
            float u = 0.7978845608028654f * (x + 0.044715f * x * x * x);
            float ge = 0.5f * x * (1.0f + tanhf(u));
            g_mid[((size_t)e * EROWS + r) * FF + c] = ge;
        }
    }
}

// ---------------- expert GEMM 2 ----------------
__global__ void egemm2_kernel(const float* __restrict__ ew2, const float* __restrict__ eb2) {
    int e = blockIdx.z;
    int cnt = g_count[e];
    int row0 = blockIdx.y * BM;
    if (row0 >= cnt) return;
    int col0 = blockIdx.x * BN;
    __shared__ float As[BK][BM];
    __shared__ float Bs[BK][BN];
    int tid = threadIdx.x;
    int tx = tid & 15, ty = tid >> 4;
    const float* W = ew2 + (size_t)e * FF * CC;   // [F,C]
    const float* A = g_mid + (size_t)e * EROWS * FF;
    float acc[4][4] = {};
    for (int k0 = 0; k0 < FF; k0 += BK) {
        #pragma unroll
        for (int i = 0; i < 4; i++) {
            int idx = tid + 256 * i;
            int r = idx >> 4, c = idx & 15;
            int gr = row0 + r;
            As[c][r] = (gr < cnt) ? A[(size_t)gr * FF + k0 + c] : 0.0f;
        }
        #pragma unroll
        for (int i = 0; i < 4; i++) {
            int idx = tid + 256 * i;
            int r = idx >> 6, c = idx & 63;
            Bs[r][c] = W[(size_t)(k0 + r) * CC + col0 + c];
        }
        __syncthreads();
        #pragma unroll
        for (int kk = 0; kk < BK; kk++) {
            float4 a4 = reinterpret_cast<const float4*>(&As[kk][0])[ty];
            float4 b4 = reinterpret_cast<const float4*>(&Bs[kk][0])[tx];
            float a[4] = {a4.x, a4.y, a4.z, a4.w};
            float bb[4] = {b4.x, b4.y, b4.z, b4.w};
            #pragma unroll
            for (int i = 0; i < 4; i++)
                #pragma unroll
                for (int j = 0; j < 4; j++)
                    acc[i][j] += a[i] * bb[j];
        }
        __syncthreads();
    }
    #pragma unroll
    for (int i = 0; i < 4; i++) {
        int r = row0 + ty * 4 + i;
        if (r >= cnt) continue;
        #pragma unroll
        for (int j = 0; j < 4; j++) {
            int c = col0 + tx * 4 + j;
            g_eo[((size_t)e * EROWS + r) * CC + c] = acc[i][j] + eb2[e * CC + c];
        }
    }
}

// ---------------- combine + aux ----------------
__global__ void combine_kernel(float* __restrict__ out) {
    int t = blockIdx.x;
    int tid = threadIdx.x;                    // 128
    int r0 = g_tokrow[t * 2], r1 = g_tokrow[t * 2 + 1];
    float g0 = g_tokgate[t * 2], g1 = g_tokgate[t * 2 + 1];
    const float* x2 = g_x2 + (size_t)t * CC;
    const float* e0 = g_eo + (size_t)r0 * CC;
    const float* e1 = g_eo + (size_t)r1 * CC;
    float* orow = out + (size_t)t * CC;
    for (int c = tid; c < CC; c += 128)
        orow[c] = x2[c] + g0 * e0[c] + g1 * e1[c];
}

__global__ void aux_kernel(float* __restrict__ out, int out_size) {
    if (threadIdx.x == 0 && blockIdx.x == 0) {
        float a = 0.0f;
        for (int e = 0; e < EE; e++)
            a += (g_count[e] / (float)TOK) * (g_Psum[e] / (float)TOK);
        a *= (float)EE;
        if (out_size > TOK * CC) out[TOK * CC] = a;
    }
}

// ---------------- launch ----------------
extern "C" void kernel_launch(void* const* d_in, const int* in_sizes, int n_in,
                              void* d_out, int out_size) {
    const float* x      = (const float*)d_in[0];
    const float* vision = (const float*)d_in[1];
    const float* ln1_g = (const float*)d_in[2];  const float* ln1_b = (const float*)d_in[3];
    const float* ln2_g = (const float*)d_in[4];  const float* ln2_b = (const float*)d_in[5];
    const float* ln3_g = (const float*)d_in[6];  const float* ln3_b = (const float*)d_in[7];
    const float* sa_wq = (const float*)d_in[8];  const float* sa_bq = (const float*)d_in[9];
    const float* sa_wk = (const float*)d_in[10]; const float* sa_bk = (const float*)d_in[11];
    const float* sa_wv = (const float*)d_in[12]; const float* sa_bv = (const float*)d_in[13];
    const float* sa_wo = (const float*)d_in[14]; const float* sa_bo = (const float*)d_in[15];
    const float* ca_wq = (const float*)d_in[16]; const float* ca_bq = (const float*)d_in[17];
    const float* ca_wk = (const float*)d_in[18]; const float* ca_bk = (const float*)d_in[19];
    const float* ca_wv = (const float*)d_in[20]; const float* ca_bv = (const float*)d_in[21];
    const float* ca_wo = (const float*)d_in[22]; const float* ca_bo = (const float*)d_in[23];
    const float* rw    = (const float*)d_in[24]; const float* rb    = (const float*)d_in[25];
    const float* ew1   = (const float*)d_in[26]; const float* eb1   = (const float*)d_in[27];
    const float* ew2   = (const float*)d_in[28]; const float* eb2   = (const float*)d_in[29];
    float* out = (float*)d_out;

    float *p_h, *p_q, *p_k, *p_v, *p_att, *p_x1, *p_x2;
    cudaGetSymbolAddress((void**)&p_h,  g_h);
    cudaGetSymbolAddress((void**)&p_q,  g_q);
    cudaGetSymbolAddress((void**)&p_k,  g_k);
    cudaGetSymbolAddress((void**)&p_v,  g_v);
    cudaGetSymbolAddress((void**)&p_att, g_att);
    cudaGetSymbolAddress((void**)&p_x1, g_x1);
    cudaGetSymbolAddress((void**)&p_x2, g_x2);

    dim3 gC(CC / BN, TOK / BM);     // 8 x 128
    dim3 gKV(KVDIM / BN, TOK / BM); // 2 x 128
    dim3 gKVv(KVDIM / BN, (BB * MV + BM - 1) / BM); // 2 x 36

    // --- block 1: pre-norm causal GQA self-attn + residual ---
    ln_kernel<<<TOK, 256>>>(x, ln1_g, ln1_b, p_h);
    gemm_kernel<<<gC, 256>>>(p_h, sa_wq, sa_bq, nullptr, p_q, TOK, CC, CC);
    gemm_kernel<<<gKV, 256>>>(p_h, sa_wk, sa_bk, nullptr, p_k, TOK, KVDIM, CC);
    gemm_kernel<<<gKV, 256>>>(p_h, sa_wv, sa_bv, nullptr, p_v, TOK, KVDIM, CC);
    attn_kernel<<<dim3(NN, HH, BB), 128>>>(p_q, p_k, p_v, p_att, NN, 1);
    gemm_kernel<<<gC, 256>>>(p_att, sa_wo, sa_bo, x, p_x1, TOK, CC, CC);

    // --- block 2: pre-norm cross-attn + residual ---
    ln_kernel<<<TOK, 256>>>(p_x1, ln2_g, ln2_b, p_h);
    gemm_kernel<<<gC, 256>>>(p_h, ca_wq, ca_bq, nullptr, p_q, TOK, CC, CC);
    gemm_kernel<<<gKVv, 256>>>(vision, ca_wk, ca_bk, nullptr, p_k, BB * MV, KVDIM, CC);
    gemm_kernel<<<gKVv, 256>>>(vision, ca_wv, ca_bv, nullptr, p_v, BB * MV, KVDIM, CC);
    attn_kernel<<<dim3(NN, HH, BB), 128>>>(p_q, p_k, p_v, p_att, MV, 0);
    gemm_kernel<<<gC, 256>>>(p_att, ca_wo, ca_bo, p_x1, p_x2, TOK, CC, CC);

    // --- block 3: pre-norm MoE + residual (sparse: only routed experts) ---
    ln_kernel<<<TOK, 256>>>(p_x2, ln3_g, ln3_b, p_h);
    zero_kernel<<<1, 32>>>();
    router_kernel<<<TOK / 256, 256>>>(rw, rb);
    egemm1_kernel<<<dim3(FF / BN, EROWS / BM, EE), 256>>>(ew1, eb1);
    egemm2_kernel<<<dim3(CC / BN, EROWS / BM, EE), 256>>>(ew2, eb2);
    combine_kernel<<<TOK, 128>>>(out);
    aux_kernel<<<1, 1>>>(out, out_size);
}

// round 3
// speedup vs baseline: 5.5237x; 5.5237x over previous
#include <cuda_runtime.h>
#include <cuda_bf16.h>
#include <math.h>

// ---------------- problem constants ----------------
#define BB 4
#define NN 2048
#define MV 576
#define CC 512
#define HH 8
#define KVH 2
#define DD 64
#define EE 8
#define TOPK 2
#define FF 2048
#define TOK (BB*NN)          // 8192 text tokens
#define KVDIM (KVH*DD)       // 128
#define EROWS 8192           // max assignments per expert

// ---------------- static scratch ----------------
__device__ float g_h  [(size_t)TOK*CC];
__device__ float g_q  [(size_t)TOK*CC];
__device__ float g_k  [(size_t)TOK*KVDIM];
__device__ float g_v  [(size_t)TOK*KVDIM];
__device__ float g_att[(size_t)TOK*CC];
__device__ float g_x1 [(size_t)TOK*CC];
__device__ float g_x2 [(size_t)TOK*CC];
__device__ float g_mid[(size_t)EE*EROWS*FF];
__device__ float g_eo [(size_t)EE*EROWS*CC];
__device__ int   g_count[EE];
__device__ float g_Psum[EE];
__device__ int   g_tokrow [TOK*TOPK];
__device__ float g_tokgate[TOK*TOPK];
__device__ int   g_tok_of_row[EE*EROWS];

// ---------------- LayerNorm: one block per row ----------------
__global__ void ln_kernel(const float* __restrict__ x, const float* __restrict__ g,
                          const float* __restrict__ b, float* __restrict__ o) {
    int t = blockIdx.x;
    int tid = threadIdx.x;                 // 256 threads, C=512
    const float* xr = x + (size_t)t * CC;
    float v0 = xr[tid], v1 = xr[tid + 256];
    __shared__ float red[256];
    red[tid] = v0 + v1; __syncthreads();
    for (int off = 128; off > 0; off >>= 1) {
        if (tid < off) red[tid] += red[tid + off];
        __syncthreads();
    }
    float mu = red[0] * (1.0f / CC);
    __syncthreads();
    float d0 = v0 - mu, d1 = v1 - mu;
    red[tid] = d0 * d0 + d1 * d1; __syncthreads();
    for (int off = 128; off > 0; off >>= 1) {
        if (tid < off) red[tid] += red[tid + off];
        __syncthreads();
    }
    float rstd = rsqrtf(red[0] * (1.0f / CC) + 1e-6f);
    float* orow = o + (size_t)t * CC;
    orow[tid]       = d0 * rstd * g[tid]       + b[tid];
    orow[tid + 256] = d1 * rstd * g[tid + 256] + b[tid + 256];
}

// ---------------- generic tiled SGEMM ----------------
#define BM 64
#define BN 64
#define BK 16
__global__ void gemm_kernel(const float* __restrict__ A, const float* __restrict__ W,
                            const float* __restrict__ bias, const float* __restrict__ resid,
                            float* __restrict__ out, int Mr, int Nc, int Kd) {
    __shared__ float As[BK][BM];
    __shared__ float Bs[BK][BN];
    int tid = threadIdx.x;                 // 256
    int tx = tid & 15, ty = tid >> 4;
    int row0 = blockIdx.y * BM;
    int col0 = blockIdx.x * BN;
    float acc[4][4] = {};
    for (int k0 = 0; k0 < Kd; k0 += BK) {
        #pragma unroll
        for (int i = 0; i < 4; i++) {
            int idx = tid + 256 * i;
            int r = idx >> 4, c = idx & 15;
            int gr = row0 + r;
            As[c][r] = (gr < Mr) ? A[(size_t)gr * Kd + k0 + c] : 0.0f;
        }
        #pragma unroll
        for (int i = 0; i < 4; i++) {
            int idx = tid + 256 * i;
            int r = idx >> 6, c = idx & 63;
            Bs[r][c] = W[(size_t)(k0 + r) * Nc + col0 + c];
        }
        __syncthreads();
        #pragma unroll
        for (int kk = 0; kk < BK; kk++) {
            float4 a4 = reinterpret_cast<const float4*>(&As[kk][0])[ty];
            float4 b4 = reinterpret_cast<const float4*>(&Bs[kk][0])[tx];
            float a[4] = {a4.x, a4.y, a4.z, a4.w};
            float bb[4] = {b4.x, b4.y, b4.z, b4.w};
            #pragma unroll
            for (int i = 0; i < 4; i++)
                #pragma unroll
                for (int j = 0; j < 4; j++)
                    acc[i][j] += a[i] * bb[j];
        }
        __syncthreads();
    }
    #pragma unroll
    for (int i = 0; i < 4; i++) {
        int r = row0 + ty * 4 + i;
        if (r >= Mr) continue;
        #pragma unroll
        for (int j = 0; j < 4; j++) {
            int c = col0 + tx * 4 + j;
            if (c >= Nc) continue;
            float v = acc[i][j];
            if (bias)  v += bias[c];
            if (resid) v += resid[(size_t)r * Nc + c];
            out[(size_t)r * Nc + c] = v;
        }
    }
}

// ---------------- flash attention: block = (64-query tile, head, batch) ----------------
// S and PV phases are 64x64x64 register-tiled GEMMs; online softmax via 16-lane shuffles.
__global__ void __launch_bounds__(256) flash_kernel(
        const float* __restrict__ Q, const float* __restrict__ K,
        const float* __restrict__ V, float* __restrict__ out,
        int n_kv, int causal) {
    int qt = blockIdx.x, h = blockIdx.y, b = blockIdx.z;
    int g = h >> 2;                        // H/KVH = 4
    __shared__ float Qs[64][64];           // transposed: Qs[d][i]
    __shared__ float KPs[64][64];          // K transposed Ks[d][j]; reused as Ps[k][i]
    __shared__ float Vs[64][64];           // direct: Vs[k][d]
    int tid = threadIdx.x;                 // 256
    int tx = tid & 15, ty = tid >> 4;
    int lrow = tid >> 2;                   // 0..63
    int dseg = (tid & 3) * 16;             // 0,16,32,48

    // load Q tile transposed
    {
        const float* qp = Q + ((size_t)(b * NN + qt * 64 + lrow)) * CC + h * DD + dseg;
        #pragma unroll
        for (int q4 = 0; q4 < 4; q4++) {
            float4 v = *(const float4*)(qp + q4 * 4);
            Qs[dseg + q4 * 4 + 0][lrow] = v.x;
            Qs[dseg + q4 * 4 + 1][lrow] = v.y;
            Qs[dseg + q4 * 4 + 2][lrow] = v.z;
            Qs[dseg + q4 * 4 + 3][lrow] = v.w;
        }
    }

    float m_i[4], l_i[4], o[4][4];
    #pragma unroll
    for (int i = 0; i < 4; i++) {
        m_i[i] = -1e30f; l_i[i] = 0.0f;
        #pragma unroll
        for (int j = 0; j < 4; j++) o[i][j] = 0.0f;
    }

    int nkt = causal ? (qt + 1) : (n_kv / 64);
    for (int kt = 0; kt < nkt; kt++) {
        __syncthreads();  // previous-iter readers of KPs/Vs done (also orders Qs stores on kt=0)
        {   // load K tile (transposed) + V tile (direct)
            const float* kp = K + ((size_t)(b * n_kv + kt * 64 + lrow)) * KVDIM + g * DD + dseg;
            const float* vp = V + ((size_t)(b * n_kv + kt * 64 + lrow)) * KVDIM + g * DD + dseg;
            #pragma unroll
            for (int q4 = 0; q4 < 4; q4++) {
                float4 kv = *(const float4*)(kp + q4 * 4);
                KPs[dseg + q4 * 4 + 0][lrow] = kv.x;
                KPs[dseg + q4 * 4 + 1][lrow] = kv.y;
                KPs[dseg + q4 * 4 + 2][lrow] = kv.z;
                KPs[dseg + q4 * 4 + 3][lrow] = kv.w;
                *(float4*)(&Vs[lrow][dseg + q4 * 4]) = *(const float4*)(vp + q4 * 4);
            }
        }
        __syncthreads();

        // S = Q @ K^T  (rows ty*4.., cols tx*4..)
        float s[4][4] = {};
        #pragma unroll
        for (int d = 0; d < 64; d++) {
            float4 qv = *(const float4*)(&Qs[d][ty * 4]);
            float4 kv = *(const float4*)(&KPs[d][tx * 4]);
            float qa[4] = {qv.x, qv.y, qv.z, qv.w};
            float ka[4] = {kv.x, kv.y, kv.z, kv.w};
            #pragma unroll
            for (int i = 0; i < 4; i++)
                #pragma unroll
                for (int j = 0; j < 4; j++)
                    s[i][j] += qa[i] * ka[j];
        }
        // scale + causal mask (diagonal tile only)
        #pragma unroll
        for (int i = 0; i < 4; i++)
            #pragma unroll
            for (int j = 0; j < 4; j++) {
                float v = s[i][j] * 0.125f;
                if (causal && kt == qt && (tx * 4 + j) > (ty * 4 + i)) v = -1e9f;
                s[i][j] = v;
            }
        // online softmax update
        #pragma unroll
        for (int i = 0; i < 4; i++) {
            float rm = fmaxf(fmaxf(s[i][0], s[i][1]), fmaxf(s[i][2], s[i][3]));
            #pragma unroll
            for (int off = 8; off; off >>= 1)
                rm = fmaxf(rm, __shfl_xor_sync(0xffffffffu, rm, off));
            float mn = fmaxf(m_i[i], rm);
            float alpha = __expf(m_i[i] - mn);
            m_i[i] = mn;
            float rs = 0.0f;
            #pragma unroll
            for (int j = 0; j < 4; j++) {
                s[i][j] = __expf(s[i][j] - mn);
                rs += s[i][j];
            }
            #pragma unroll
            for (int off = 8; off; off >>= 1)
                rs += __shfl_xor_sync(0xffffffffu, rs, off);
            l_i[i] = l_i[i] * alpha + rs;
            #pragma unroll
            for (int j = 0; j < 4; j++) o[i][j] *= alpha;
        }
        __syncthreads();  // all threads done reading KPs as K
        // store P transposed: Ps[k][i]
        #pragma unroll
        for (int i = 0; i < 4; i++)
            #pragma unroll
            for (int j = 0; j < 4; j++)
                KPs[tx * 4 + j][ty * 4 + i] = s[i][j];
        __syncthreads();
        // O += P @ V
        #pragma unroll
        for (int k = 0; k < 64; k++) {
            float4 pv = *(const float4*)(&KPs[k][ty * 4]);
            float4 vv = *(const float4*)(&Vs[k][tx * 4]);
            float pa[4] = {pv.x, pv.y, pv.z, pv.w};
            float va[4] = {vv.x, vv.y, vv.z, vv.w};
            #pragma unroll
            for (int i = 0; i < 4; i++)
                #pragma unroll
                for (int j = 0; j < 4; j++)
                    o[i][j] += pa[i] * va[j];
        }
    }
    // epilogue: normalize and store
    #pragma unroll
    for (int i = 0; i < 4; i++) {
        float inv = 1.0f / l_i[i];
        int row = qt * 64 + ty * 4 + i;
        float4 w = make_float4(o[i][0] * inv, o[i][1] * inv, o[i][2] * inv, o[i][3] * inv);
        *(float4*)(&out[((size_t)(b * NN + row)) * CC + h * DD + tx * 4]) = w;
    }
}

// ---------------- MoE routing ----------------
__global__ void zero_kernel() {
    int t = threadIdx.x;
    if (t < EE) { g_count[t] = 0; g_Psum[t] = 0.0f; }
}

__global__ void router_kernel(const float* __restrict__ rw, const float* __restrict__ rb) {
    __shared__ float sP[EE];
    int tid = threadIdx.x;
    if (tid < EE) sP[tid] = 0.0f;
    __syncthreads();
    int t = blockIdx.x * blockDim.x + tid;
    float logit[EE];
    const float* hrow = g_h + (size_t)t * CC;
    #pragma unroll
    for (int e = 0; e < EE; e++) logit[e] = rb[e];
    for (int k = 0; k < CC; k++) {
        float hv = hrow[k];
        const float* wr = rw + k * EE;
        #pragma unroll
        for (int e = 0; e < EE; e++) logit[e] += hv * wr[e];
    }
    float mx = logit[0];
    #pragma unroll
    for (int e = 1; e < EE; e++) mx = fmaxf(mx, logit[e]);
    float p[EE], ps = 0.0f;
    #pragma unroll
    for (int e = 0; e < EE; e++) { p[e] = __expf(logit[e] - mx); ps += p[e]; }
    float invs = 1.0f / ps;
    #pragma unroll
    for (int e = 0; e < EE; e++) p[e] *= invs;
    int i0 = 0;
    #pragma unroll
    for (int e = 1; e < EE; e++) if (p[e] > p[i0]) i0 = e;
    int i1 = (i0 == 0) ? 1 : 0;
    #pragma unroll
    for (int e = 0; e < EE; e++) if (e != i0 && p[e] > p[i1]) i1 = e;
    float gs = p[i0] + p[i1];
    float g0 = p[i0] / gs, g1 = p[i1] / gs;
    int s0 = atomicAdd(&g_count[i0], 1);
    int s1 = atomicAdd(&g_count[i1], 1);
    int r0 = i0 * EROWS + s0, r1 = i1 * EROWS + s1;
    g_tok_of_row[r0] = t; g_tok_of_row[r1] = t;
    g_tokrow[t * 2] = r0; g_tokrow[t * 2 + 1] = r1;
    g_tokgate[t * 2] = g0; g_tokgate[t * 2 + 1] = g1;
    #pragma unroll
    for (int e = 0; e < EE; e++) atomicAdd(&sP[e], p[e]);
    __syncthreads();
    if (tid < EE) atomicAdd(&g_Psum[tid], sP[tid]);
}

// ---------------- expert GEMM 1 (gathered A, GELU) ----------------
__global__ void egemm1_kernel(const float* __restrict__ ew1, const float* __restrict__ eb1) {
    int e = blockIdx.z;
    int cnt = g_count[e];
    int row0 = blockIdx.y * BM;
    if (row0 >= cnt) return;
    int col0 = blockIdx.x * BN;
    __shared__ float As[BK][BM];
    __shared__ float Bs[BK][BN];
    __shared__ int s_tok[BM];
    int tid = threadIdx.x;
    if (tid < BM) {
        int gr = row0 + tid;
        s_tok[tid] = (gr < cnt) ? g_tok_of_row[e * EROWS + gr] : -1;
    }
    __syncthreads();
    int tx = tid & 15, ty = tid >> 4;
    const float* W = ew1 + (size_t)e * CC * FF;
    float acc[4][4] = {};
    for (int k0 = 0; k0 < CC; k0 += BK) {
        #pragma unroll
        for (int i = 0; i < 4; i++) {
            int idx = tid + 256 * i;
            int r = idx >> 4, c = idx & 15;
            int tok = s_tok[r];
            As[c][r] = (tok >= 0) ? g_h[(size_t)tok * CC + k0 + c] : 0.0f;
        }
        #pragma unroll
        for (int i = 0; i < 4; i++) {
            int idx = tid + 256 * i;
            int r = idx >> 6, c = idx & 63;
            Bs[r][c] = W[(size_t)(k0 + r) * FF + col0 + c];
        }
        __syncthreads();
        #pragma unroll
        for (int kk = 0; kk < BK; kk++) {
            float4 a4 = reinterpret_cast<const float4*>(&As[kk][0])[ty];
            float4 b4 = reinterpret_cast<const float4*>(&Bs[kk][0])[tx];
            float a[4] = {a4.x, a4.y, a4.z, a4.w};
            float bb[4] = {b4.x, b4.y, b4.z, b4.w};
            #pragma unroll
            for (int i = 0; i < 4; i++)
                #pragma unroll
                for (int j = 0; j < 4; j++)
                    acc[i][j] += a[i] * bb[j];
        }
        __syncthreads();
    }
    #pragma unroll
    for (int i = 0; i < 4; i++) {
        int r = row0 + ty * 4 + i;
        if (r >= cnt) continue;
        #pragma unroll
        for (int j = 0; j < 4; j++) {
            int c = col0 + tx * 4 + j;
            float x = acc[i][j] + eb1[e * FF + c];
            float u = 0.7978845608028654f * (x + 0.044715f * x * x * x);
            float ge = 0.5f * x * (1.0f + tanhf(u));
            g_mid[((size_t)e * EROWS + r) * FF + c] = ge;
        }
    }
}

// ---------------- expert GEMM 2 ----------------
__global__ void egemm2_kernel(const float* __restrict__ ew2, const float* __restrict__ eb2) {
    int e = blockIdx.z;
    int cnt = g_count[e];
    int row0 = blockIdx.y * BM;
    if (row0 >= cnt) return;
    int col0 = blockIdx.x * BN;
    __shared__ float As[BK][BM];
    __shared__ float Bs[BK][BN];
    int tid = threadIdx.x;
    int tx = tid & 15, ty = tid >> 4;
    const float* W = ew2 + (size_t)e * FF * CC;
    const float* A = g_mid + (size_t)e * EROWS * FF;
    float acc[4][4] = {};
    for (int k0 = 0; k0 < FF; k0 += BK) {
        #pragma unroll
        for (int i = 0; i < 4; i++) {
            int idx = tid + 256 * i;
            int r = idx >> 4, c = idx & 15;
            int gr = row0 + r;
            As[c][r] = (gr < cnt) ? A[(size_t)gr * FF + k0 + c] : 0.0f;
        }
        #pragma unroll
        for (int i = 0; i < 4; i++) {
            int idx = tid + 256 * i;
            int r = idx >> 6, c = idx & 63;
            Bs[r][c] = W[(size_t)(k0 + r) * CC + col0 + c];
        }
        __syncthreads();
        #pragma unroll
        for (int kk = 0; kk < BK; kk++) {
            float4 a4 = reinterpret_cast<const float4*>(&As[kk][0])[ty];
            float4 b4 = reinterpret_cast<const float4*>(&Bs[kk][0])[tx];
            float a[4] = {a4.x, a4.y, a4.z, a4.w};
            float bb[4] = {b4.x, b4.y, b4.z, b4.w};
            #pragma unroll
            for (int i = 0; i < 4; i++)
                #pragma unroll
                for (int j = 0; j < 4; j++)
                    acc[i][j] += a[i] * bb[j];
        }
        __syncthreads();
    }
    #pragma unroll
    for (int i = 0; i < 4; i++) {
        int r = row0 + ty * 4 + i;
        if (r >= cnt) continue;
        #pragma unroll
        for (int j = 0; j < 4; j++) {
            int c = col0 + tx * 4 + j;
            g_eo[((size_t)e * EROWS + r) * CC + c] = acc[i][j] + eb2[e * CC + c];
        }
    }
}

// ---------------- combine + aux ----------------
__global__ void combine_kernel(float* __restrict__ out) {
    int t = blockIdx.x;
    int tid = threadIdx.x;
    int r0 = g_tokrow[t * 2], r1 = g_tokrow[t * 2 + 1];
    float g0 = g_tokgate[t * 2], g1 = g_tokgate[t * 2 + 1];
    const float* x2 = g_x2 + (size_t)t * CC;
    const float* e0 = g_eo + (size_t)r0 * CC;
    const float* e1 = g_eo + (size_t)r1 * CC;
    float* orow = out + (size_t)t * CC;
    for (int c = tid; c < CC; c += 128)
        orow[c] = x2[c] + g0 * e0[c] + g1 * e1[c];
}

__global__ void aux_kernel(float* __restrict__ out, int out_size) {
    if (threadIdx.x == 0 && blockIdx.x == 0) {
        float a = 0.0f;
        for (int e = 0; e < EE; e++)
            a += (g_count[e] / (float)TOK) * (g_Psum[e] / (float)TOK);
        a *= (float)EE;
        if (out_size > TOK * CC) out[TOK * CC] = a;
    }
}

// ---------------- launch ----------------
extern "C" void kernel_launch(void* const* d_in, const int* in_sizes, int n_in,
                              void* d_out, int out_size) {
    const float* x      = (const float*)d_in[0];
    const float* vision = (const float*)d_in[1];
    const float* ln1_g = (const float*)d_in[2];  const float* ln1_b = (const float*)d_in[3];
    const float* ln2_g = (const float*)d_in[4];  const float* ln2_b = (const float*)d_in[5];
    const float* ln3_g = (const float*)d_in[6];  const float* ln3_b = (const float*)d_in[7];
    const float* sa_wq = (const float*)d_in[8];  const float* sa_bq = (const float*)d_in[9];
    const float* sa_wk = (const float*)d_in[10]; const float* sa_bk = (const float*)d_in[11];
    const float* sa_wv = (const float*)d_in[12]; const float* sa_bv = (const float*)d_in[13];
    const float* sa_wo = (const float*)d_in[14]; const float* sa_bo = (const float*)d_in[15];
    const float* ca_wq = (const float*)d_in[16]; const float* ca_bq = (const float*)d_in[17];
    const float* ca_wk = (const float*)d_in[18]; const float* ca_bk = (const float*)d_in[19];
    const float* ca_wv = (const float*)d_in[20]; const float* ca_bv = (const float*)d_in[21];
    const float* ca_wo = (const float*)d_in[22]; const float* ca_bo = (const float*)d_in[23];
    const float* rw    = (const float*)d_in[24]; const float* rb    = (const float*)d_in[25];
    const float* ew1   = (const float*)d_in[26]; const float* eb1   = (const float*)d_in[27];
    const float* ew2   = (const float*)d_in[28]; const float* eb2   = (const float*)d_in[29];
    float* out = (float*)d_out;

    float *p_h, *p_q, *p_k, *p_v, *p_att, *p_x1, *p_x2;
    cudaGetSymbolAddress((void**)&p_h,  g_h);
    cudaGetSymbolAddress((void**)&p_q,  g_q);
    cudaGetSymbolAddress((void**)&p_k,  g_k);
    cudaGetSymbolAddress((void**)&p_v,  g_v);
    cudaGetSymbolAddress((void**)&p_att, g_att);
    cudaGetSymbolAddress((void**)&p_x1, g_x1);
    cudaGetSymbolAddress((void**)&p_x2, g_x2);

    dim3 gC(CC / BN, TOK / BM);     // 8 x 128
    dim3 gKV(KVDIM / BN, TOK / BM); // 2 x 128
    dim3 gKVv(KVDIM / BN, (BB * MV + BM - 1) / BM); // 2 x 36
    dim3 gAtt(NN / 64, HH, BB);     // 32 x 8 x 4

    // --- block 1: pre-norm causal GQA self-attn + residual ---
    ln_kernel<<<TOK, 256>>>(x, ln1_g, ln1_b, p_h);
    gemm_kernel<<<gC, 256>>>(p_h, sa_wq, sa_bq, nullptr, p_q, TOK, CC, CC);
    gemm_kernel<<<gKV, 256>>>(p_h, sa_wk, sa_bk, nullptr, p_k, TOK, KVDIM, CC);
    gemm_kernel<<<gKV, 256>>>(p_h, sa_wv, sa_bv, nullptr, p_v, TOK, KVDIM, CC);
    flash_kernel<<<gAtt, 256>>>(p_q, p_k, p_v, p_att, NN, 1);
    gemm_kernel<<<gC, 256>>>(p_att, sa_wo, sa_bo, x, p_x1, TOK, CC, CC);

    // --- block 2: pre-norm cross-attn + residual ---
    ln_kernel<<<TOK, 256>>>(p_x1, ln2_g, ln2_b, p_h);
    gemm_kernel<<<gC, 256>>>(p_h, ca_wq, ca_bq, nullptr, p_q, TOK, CC, CC);
    gemm_kernel<<<gKVv, 256>>>(vision, ca_wk, ca_bk, nullptr, p_k, BB * MV, KVDIM, CC);
    gemm_kernel<<<gKVv, 256>>>(vision, ca_wv, ca_bv, nullptr, p_v, BB * MV, KVDIM, CC);
    flash_kernel<<<gAtt, 256>>>(p_q, p_k, p_v, p_att, MV, 0);
    gemm_kernel<<<gC, 256>>>(p_att, ca_wo, ca_bo, p_x1, p_x2, TOK, CC, CC);

    // --- block 3: pre-norm MoE + residual (sparse: only routed experts) ---
    ln_kernel<<<TOK, 256>>>(p_x2, ln3_g, ln3_b, p_h);
    zero_kernel<<<1, 32>>>();
    router_kernel<<<TOK / 256, 256>>>(rw, rb);
    egemm1_kernel<<<dim3(FF / BN, EROWS / BM, EE), 256>>>(ew1, eb1);
    egemm2_kernel<<<dim3(CC / BN, EROWS / BM, EE), 256>>>(ew2, eb2);
    combine_kernel<<<TOK, 128>>>(out);
    aux_kernel<<<1, 1>>>(out, out_size);
}

// round 5
// speedup vs baseline: 8.6458x; 1.5652x over previous
#include <cuda_runtime.h>
#include <cuda_bf16.h>
#include <math.h>

// ---------------- problem constants ----------------
#define BB 4
#define NN 2048
#define MV 576
#define CC 512
#define HH 8
#define KVH 2
#define DD 64
#define EE 8
#define TOPK 2
#define FF 2048
#define TOK (BB*NN)          // 8192 text tokens
#define KVDIM (KVH*DD)       // 128
#define EROWS 8192           // max assignments per expert

// ---------------- static scratch ----------------
__device__ float g_h  [(size_t)TOK*CC];
__device__ float g_q  [(size_t)TOK*CC];
__device__ float g_k  [(size_t)TOK*KVDIM];
__device__ float g_v  [(size_t)TOK*KVDIM];
__device__ float g_att[(size_t)TOK*CC];
__device__ float g_x1 [(size_t)TOK*CC];
__device__ float g_x2 [(size_t)TOK*CC];
__device__ float g_mid[(size_t)EE*EROWS*FF];
__device__ float g_eo [(size_t)EE*EROWS*CC];
__device__ int   g_count[EE];
__device__ float g_Psum[EE];
__device__ int   g_tokrow [TOK*TOPK];
__device__ float g_tokgate[TOK*TOPK];
__device__ int   g_tok_of_row[EE*EROWS];

// ---------------- LayerNorm ----------------
__global__ void ln_kernel(const float* __restrict__ x, const float* __restrict__ g,
                          const float* __restrict__ b, float* __restrict__ o) {
    int t = blockIdx.x;
    int tid = threadIdx.x;                 // 256 threads, C=512
    const float* xr = x + (size_t)t * CC;
    float v0 = xr[tid], v1 = xr[tid + 256];
    __shared__ float red[256];
    red[tid] = v0 + v1; __syncthreads();
    for (int off = 128; off > 0; off >>= 1) {
        if (tid < off) red[tid] += red[tid + off];
        __syncthreads();
    }
    float mu = red[0] * (1.0f / CC);
    __syncthreads();
    float d0 = v0 - mu, d1 = v1 - mu;
    red[tid] = d0 * d0 + d1 * d1; __syncthreads();
    for (int off = 128; off > 0; off >>= 1) {
        if (tid < off) red[tid] += red[tid + off];
        __syncthreads();
    }
    float rstd = rsqrtf(red[0] * (1.0f / CC) + 1e-6f);
    float* orow = o + (size_t)t * CC;
    orow[tid]       = d0 * rstd * g[tid]       + b[tid];
    orow[tid + 256] = d1 * rstd * g[tid + 256] + b[tid + 256];
}

// ---------------- 128x128x16 SGEMM core, 8x8 per thread ----------------
// As transposed+padded: As[k][row], Bs direct: Bs[k][col].
__device__ __forceinline__ void sgemm_tile(
        const float* __restrict__ A, const float* __restrict__ W,
        int Mr, int Nc, int Kd, int row0, int col0,
        float (*As)[132], float (*Bs)[128], float (&acc)[8][8]) {
    int tid = threadIdx.x;
    int tx = tid & 15, ty = tid >> 4;
    for (int k0 = 0; k0 < Kd; k0 += 16) {
        #pragma unroll
        for (int u = 0; u < 2; u++) {
            int f = tid + u * 256;
            int r = f >> 2, kc = (f & 3) * 4;
            int gr = row0 + r;
            float4 v = (gr < Mr) ? *(const float4*)(A + (size_t)gr * Kd + k0 + kc)
                                 : make_float4(0.f, 0.f, 0.f, 0.f);
            As[kc + 0][r] = v.x; As[kc + 1][r] = v.y;
            As[kc + 2][r] = v.z; As[kc + 3][r] = v.w;
        }
        #pragma unroll
        for (int u = 0; u < 2; u++) {
            int f = tid + u * 256;
            int r = f >> 5, c = (f & 31) * 4;
            *(float4*)&Bs[r][c] = *(const float4*)(W + (size_t)(k0 + r) * Nc + col0 + c);
        }
        __syncthreads();
        #pragma unroll
        for (int kk = 0; kk < 16; kk++) {
            float4 a0 = *(const float4*)&As[kk][ty * 4];
            float4 a1 = *(const float4*)&As[kk][ty * 4 + 64];
            float4 b0 = *(const float4*)&Bs[kk][tx * 4];
            float4 b1 = *(const float4*)&Bs[kk][tx * 4 + 64];
            float av[8] = {a0.x, a0.y, a0.z, a0.w, a1.x, a1.y, a1.z, a1.w};
            float bv[8] = {b0.x, b0.y, b0.z, b0.w, b1.x, b1.y, b1.z, b1.w};
            #pragma unroll
            for (int i = 0; i < 8; i++)
                #pragma unroll
                for (int j = 0; j < 8; j++)
                    acc[i][j] += av[i] * bv[j];
        }
        __syncthreads();
    }
}

// gathered-A variant (rows via s_tok indices into Abase)
__device__ __forceinline__ void sgemm_tile_gather(
        const int* __restrict__ s_tok, const float* __restrict__ Abase,
        const float* __restrict__ W, int Nc, int Kd, int col0,
        float (*As)[132], float (*Bs)[128], float (&acc)[8][8]) {
    int tid = threadIdx.x;
    int tx = tid & 15, ty = tid >> 4;
    for (int k0 = 0; k0 < Kd; k0 += 16) {
        #pragma unroll
        for (int u = 0; u < 2; u++) {
            int f = tid + u * 256;
            int r = f >> 2, kc = (f & 3) * 4;
            int tok = s_tok[r];
            float4 v = (tok >= 0) ? *(const float4*)(Abase + (size_t)tok * Kd + k0 + kc)
                                  : make_float4(0.f, 0.f, 0.f, 0.f);
            As[kc + 0][r] = v.x; As[kc + 1][r] = v.y;
            As[kc + 2][r] = v.z; As[kc + 3][r] = v.w;
        }
        #pragma unroll
        for (int u = 0; u < 2; u++) {
            int f = tid + u * 256;
            int r = f >> 5, c = (f & 31) * 4;
            *(float4*)&Bs[r][c] = *(const float4*)(W + (size_t)(k0 + r) * Nc + col0 + c);
        }
        __syncthreads();
        #pragma unroll
        for (int kk = 0; kk < 16; kk++) {
            float4 a0 = *(const float4*)&As[kk][ty * 4];
            float4 a1 = *(const float4*)&As[kk][ty * 4 + 64];
            float4 b0 = *(const float4*)&Bs[kk][tx * 4];
            float4 b1 = *(const float4*)&Bs[kk][tx * 4 + 64];
            float av[8] = {a0.x, a0.y, a0.z, a0.w, a1.x, a1.y, a1.z, a1.w};
            float bv[8] = {b0.x, b0.y, b0.z, b0.w, b1.x, b1.y, b1.z, b1.w};
            #pragma unroll
            for (int i = 0; i < 8; i++)
                #pragma unroll
                for (int j = 0; j < 8; j++)
                    acc[i][j] += av[i] * bv[j];
        }
        __syncthreads();
    }
}

// ---------------- generic GEMM kernel (bias + optional residual) ----------------
__global__ void __launch_bounds__(256) gemm128(
        const float* __restrict__ A, const float* __restrict__ W,
        const float* __restrict__ bias, const float* __restrict__ resid,
        float* __restrict__ out, int Mr, int Nc, int Kd) {
    __shared__ float As[16][132];
    __shared__ float Bs[16][128];
    int tid = threadIdx.x, tx = tid & 15, ty = tid >> 4;
    int row0 = blockIdx.y * 128, col0 = blockIdx.x * 128;
    float acc[8][8] = {};
    sgemm_tile(A, W, Mr, Nc, Kd, row0, col0, As, Bs, acc);
    #pragma unroll
    for (int i = 0; i < 8; i++) {
        int r = row0 + ((i < 4) ? (ty * 4 + i) : (64 + ty * 4 + i - 4));
        if (r >= Mr) continue;
        #pragma unroll
        for (int jh = 0; jh < 2; jh++) {
            int c = col0 + tx * 4 + jh * 64;
            float4 v;
            v.x = acc[i][jh * 4 + 0]; v.y = acc[i][jh * 4 + 1];
            v.z = acc[i][jh * 4 + 2]; v.w = acc[i][jh * 4 + 3];
            if (bias) {
                v.x += bias[c]; v.y += bias[c + 1]; v.z += bias[c + 2]; v.w += bias[c + 3];
            }
            if (resid) {
                const float4 rr = *(const float4*)(resid + (size_t)r * Nc + c);
                v.x += rr.x; v.y += rr.y; v.z += rr.z; v.w += rr.w;
            }
            *(float4*)(out + (size_t)r * Nc + c) = v;
        }
    }
}

// ---------------- fused K+V projection (Nc = 128, blockIdx.x selects K or V) ----------------
__global__ void __launch_bounds__(256) kvgemm128(
        const float* __restrict__ A,
        const float* __restrict__ Wk, const float* __restrict__ bk,
        const float* __restrict__ Wv, const float* __restrict__ bv,
        float* __restrict__ outk, float* __restrict__ outv, int Mr, int Kd) {
    __shared__ float As[16][132];
    __shared__ float Bs[16][128];
    const float* W    = (blockIdx.x == 0) ? Wk : Wv;
    const float* bias = (blockIdx.x == 0) ? bk : bv;
    float* out        = (blockIdx.x == 0) ? outk : outv;
    int tid = threadIdx.x, tx = tid & 15, ty = tid >> 4;
    int row0 = blockIdx.y * 128;
    float acc[8][8] = {};
    sgemm_tile(A, W, Mr, KVDIM, Kd, row0, 0, As, Bs, acc);
    #pragma unroll
    for (int i = 0; i < 8; i++) {
        int r = row0 + ((i < 4) ? (ty * 4 + i) : (64 + ty * 4 + i - 4));
        if (r >= Mr) continue;
        #pragma unroll
        for (int jh = 0; jh < 2; jh++) {
            int c = tx * 4 + jh * 64;
            float4 v;
            v.x = acc[i][jh * 4 + 0] + bias[c];
            v.y = acc[i][jh * 4 + 1] + bias[c + 1];
            v.z = acc[i][jh * 4 + 2] + bias[c + 2];
            v.w = acc[i][jh * 4 + 3] + bias[c + 3];
            *(float4*)(out + (size_t)r * KVDIM + c) = v;
        }
    }
}

// ---------------- flash attention: 128-query x 64-key tiles, 8x4 acc ----------------
// dynamic smem: Qs[64][132] (Q^T), KP[64][132] (K^T then P^T), Vs[64][68]
#define FLASH_SMEM_FLOATS (2*64*132 + 64*68)
__global__ void __launch_bounds__(256) flash_kernel(
        const float* __restrict__ Q, const float* __restrict__ K,
        const float* __restrict__ V, float* __restrict__ out,
        int n_kv, int causal) {
    extern __shared__ float sm[];
    float (*Qs)[132] = (float(*)[132])sm;
    float (*KP)[132] = (float(*)[132])(sm + 64 * 132);
    float (*Vs)[68]  = (float(*)[68])(sm + 2 * 64 * 132);
    int qt = blockIdx.x, h = blockIdx.y, b = blockIdx.z;
    int g = h >> 2;                        // H/KVH = 4
    int tid = threadIdx.x;
    int tx = tid & 15, ty = tid >> 4;

    // load Q tile (128 rows x 64 d) transposed
    {
        int qrow = tid >> 1;
        int dh = (tid & 1) * 32;
        const float* qp = Q + ((size_t)(b * NN + qt * 128 + qrow)) * CC + h * DD + dh;
        #pragma unroll
        for (int i = 0; i < 8; i++) {
            float4 v = *(const float4*)(qp + i * 4);
            Qs[dh + i * 4 + 0][qrow] = v.x;
            Qs[dh + i * 4 + 1][qrow] = v.y;
            Qs[dh + i * 4 + 2][qrow] = v.z;
            Qs[dh + i * 4 + 3][qrow] = v.w;
        }
    }

    float m_i[8], l_i[8], o[8][4];
    #pragma unroll
    for (int i = 0; i < 8; i++) {
        m_i[i] = -1e30f; l_i[i] = 0.0f;
        #pragma unroll
        for (int j = 0; j < 4; j++) o[i][j] = 0.0f;
    }

    int lrow = tid >> 2;                   // 0..63
    int dseg = (tid & 3) * 16;             // 0,16,32,48
    int nkt = causal ? (2 * qt + 2) : (n_kv / 64);
    for (int kt = 0; kt < nkt; kt++) {
        __syncthreads();  // prior readers of KP/Vs done (also orders Qs stores on kt=0)
        {   // load K tile transposed + V tile direct
            const float* kp = K + ((size_t)(b * n_kv + kt * 64 + lrow)) * KVDIM + g * DD + dseg;
            const float* vp = V + ((size_t)(b * n_kv + kt * 64 + lrow)) * KVDIM + g * DD + dseg;
            #pragma unroll
            for (int q4 = 0; q4 < 4; q4++) {
                float4 kv = *(const float4*)(kp + q4 * 4);
                KP[dseg + q4 * 4 + 0][lrow] = kv.x;
                KP[dseg + q4 * 4 + 1][lrow] = kv.y;
                KP[dseg + q4 * 4 + 2][lrow] = kv.z;
                KP[dseg + q4 * 4 + 3][lrow] = kv.w;
                *(float4*)(&Vs[lrow][dseg + q4 * 4]) = *(const float4*)(vp + q4 * 4);
            }
        }
        __syncthreads();

        // S = Q @ K^T : 8 rows x 4 cols per thread
        float s[8][4] = {};
        #pragma unroll
        for (int d = 0; d < 64; d++) {
            float4 a0 = *(const float4*)(&Qs[d][ty * 4]);
            float4 a1 = *(const float4*)(&Qs[d][ty * 4 + 64]);
            float4 bb = *(const float4*)(&KP[d][tx * 4]);
            float av[8] = {a0.x, a0.y, a0.z, a0.w, a1.x, a1.y, a1.z, a1.w};
            float bv[4] = {bb.x, bb.y, bb.z, bb.w};
            #pragma unroll
            for (int i = 0; i < 8; i++)
                #pragma unroll
                for (int j = 0; j < 4; j++)
                    s[i][j] += av[i] * bv[j];
        }
        // scale + causal mask (only tiles overlapping the diagonal)
        bool maskit = causal && (kt >= 2 * qt);
        #pragma unroll
        for (int i = 0; i < 8; i++) {
            int rg = qt * 128 + ((i < 4) ? (ty * 4 + i) : (64 + ty * 4 + i - 4));
            #pragma unroll
            for (int j = 0; j < 4; j++) {
                float v = s[i][j] * 0.125f;
                if (maskit && (kt * 64 + tx * 4 + j) > rg) v = -1e9f;
                s[i][j] = v;
            }
        }
        // online softmax (16-lane reductions across tx)
        #pragma unroll
        for (int i = 0; i < 8; i++) {
            float rm = fmaxf(fmaxf(s[i][0], s[i][1]), fmaxf(s[i][2], s[i][3]));
            #pragma unroll
            for (int off = 8; off; off >>= 1)
                rm = fmaxf(rm, __shfl_xor_sync(0xffffffffu, rm, off));
            float mn = fmaxf(m_i[i], rm);
            float alpha = __expf(m_i[i] - mn);
            m_i[i] = mn;
            float rs = 0.0f;
            #pragma unroll
            for (int j = 0; j < 4; j++) {
                s[i][j] = __expf(s[i][j] - mn);
                rs += s[i][j];
            }
            #pragma unroll
            for (int off = 8; off; off >>= 1)
                rs += __shfl_xor_sync(0xffffffffu, rs, off);
            l_i[i] = l_i[i] * alpha + rs;
            #pragma unroll
            for (int j = 0; j < 4; j++) o[i][j] *= alpha;
        }
        __syncthreads();  // all threads done reading KP as K
        // store P transposed: KP[kcol][qrow]
        #pragma unroll
        for (int i = 0; i < 8; i++) {
            int qr = (i < 4) ? (ty * 4 + i) : (64 + ty * 4 + i - 4);
            #pragma unroll
            for (int j = 0; j < 4; j++)
                KP[tx * 4 + j][qr] = s[i][j];
        }
        __syncthreads();
        // O += P @ V
        #pragma unroll
        for (int k = 0; k < 64; k++) {
            float4 p0 = *(const float4*)(&KP[k][ty * 4]);
            float4 p1 = *(const float4*)(&KP[k][ty * 4 + 64]);
            float4 vv = *(const float4*)(&Vs[k][tx * 4]);
            float pv[8] = {p0.x, p0.y, p0.z, p0.w, p1.x, p1.y, p1.z, p1.w};
            float va[4] = {vv.x, vv.y, vv.z, vv.w};
            #pragma unroll
            for (int i = 0; i < 8; i++)
                #pragma unroll
                for (int j = 0; j < 4; j++)
                    o[i][j] += pv[i] * va[j];
        }
    }
    // epilogue
    #pragma unroll
    for (int i = 0; i < 8; i++) {
        float inv = 1.0f / l_i[i];
        int row = qt * 128 + ((i < 4) ? (ty * 4 + i) : (64 + ty * 4 + i - 4));
        float4 w = make_float4(o[i][0] * inv, o[i][1] * inv, o[i][2] * inv, o[i][3] * inv);
        *(float4*)(&out[((size_t)(b * NN + row)) * CC + h * DD + tx * 4]) = w;
    }
}

// ---------------- MoE routing ----------------
__global__ void zero_kernel() {
    int t = threadIdx.x;
    if (t < EE) { g_count[t] = 0; g_Psum[t] = 0.0f; }
}

__global__ void router_kernel(const float* __restrict__ rw, const float* __restrict__ rb) {
    __shared__ float sP[EE];
    int tid = threadIdx.x;
    if (tid < EE) sP[tid] = 0.0f;
    __syncthreads();
    int t = blockIdx.x * blockDim.x + tid;
    float logit[EE];
    const float* hrow = g_h + (size_t)t * CC;
    #pragma unroll
    for (int e = 0; e < EE; e++) logit[e] = rb[e];
    for (int k = 0; k < CC; k++) {
        float hv = hrow[k];
        const float* wr = rw + k * EE;
        #pragma unroll
        for (int e = 0; e < EE; e++) logit[e] += hv * wr[e];
    }
    float mx = logit[0];
    #pragma unroll
    for (int e = 1; e < EE; e++) mx = fmaxf(mx, logit[e]);
    float p[EE], ps = 0.0f;
    #pragma unroll
    for (int e = 0; e < EE; e++) { p[e] = __expf(logit[e] - mx); ps += p[e]; }
    float invs = 1.0f / ps;
    #pragma unroll
    for (int e = 0; e < EE; e++) p[e] *= invs;
    int i0 = 0;
    #pragma unroll
    for (int e = 1; e < EE; e++) if (p[e] > p[i0]) i0 = e;
    int i1 = (i0 == 0) ? 1 : 0;
    #pragma unroll
    for (int e = 0; e < EE; e++) if (e != i0 && p[e] > p[i1]) i1 = e;
    float gs = p[i0] + p[i1];
    float g0 = p[i0] / gs, g1 = p[i1] / gs;
    int s0 = atomicAdd(&g_count[i0], 1);
    int s1 = atomicAdd(&g_count[i1], 1);
    int r0 = i0 * EROWS + s0, r1 = i1 * EROWS + s1;
    g_tok_of_row[r0] = t; g_tok_of_row[r1] = t;
    g_tokrow[t * 2] = r0; g_tokrow[t * 2 + 1] = r1;
    g_tokgate[t * 2] = g0; g_tokgate[t * 2 + 1] = g1;
    #pragma unroll
    for (int e = 0; e < EE; e++) atomicAdd(&sP[e], p[e]);
    __syncthreads();
    if (tid < EE) atomicAdd(&g_Psum[tid], sP[tid]);
}

// ---------------- expert GEMM 1 (gathered A, GELU) ----------------
__global__ void __launch_bounds__(256) egemm1_kernel(const float* __restrict__ ew1,
                                                     const float* __restrict__ eb1) {
    int e = blockIdx.z;
    int cnt = g_count[e];
    int row0 = blockIdx.y * 128;
    if (row0 >= cnt) return;
    int col0 = blockIdx.x * 128;
    __shared__ float As[16][132];
    __shared__ float Bs[16][128];
    __shared__ int s_tok[128];
    int tid = threadIdx.x, tx = tid & 15, ty = tid >> 4;
    if (tid < 128) {
        int gr = row0 + tid;
        s_tok[tid] = (gr < cnt) ? g_tok_of_row[e * EROWS + gr] : -1;
    }
    __syncthreads();
    float acc[8][8] = {};
    sgemm_tile_gather(s_tok, g_h, ew1 + (size_t)e * CC * FF, FF, CC, col0, As, Bs, acc);
    #pragma unroll
    for (int i = 0; i < 8; i++) {
        int rl = (i < 4) ? (ty * 4 + i) : (64 + ty * 4 + i - 4);
        int r = row0 + rl;
        if (r >= cnt) continue;
        #pragma unroll
        for (int jh = 0; jh < 2; jh++) {
            #pragma unroll
            for (int j = 0; j < 4; j++) {
                int c = col0 + tx * 4 + jh * 64 + j;
                float x = acc[i][jh * 4 + j] + eb1[e * FF + c];
                float u = 0.7978845608028654f * (x + 0.044715f * x * x * x);
                float ge = 0.5f * x * (1.0f + tanhf(u));
                g_mid[((size_t)e * EROWS + r) * FF + c] = ge;
            }
        }
    }
}

// ---------------- expert GEMM 2 ----------------
__global__ void __launch_bounds__(256) egemm2_kernel(const float* __restrict__ ew2,
                                                     const float* __restrict__ eb2) {
    int e = blockIdx.z;
    int cnt = g_count[e];
    int row0 = blockIdx.y * 128;
    if (row0 >= cnt) return;
    int col0 = blockIdx.x * 128;
    __shared__ float As[16][132];
    __shared__ float Bs[16][128];
    int tid = threadIdx.x, tx = tid & 15, ty = tid >> 4;
    float acc[8][8] = {};
    sgemm_tile(g_mid + (size_t)e * EROWS * FF, ew2 + (size_t)e * FF * CC,
               cnt, CC, FF, row0, col0, As, Bs, acc);
    #pragma unroll
    for (int i = 0; i < 8; i++) {
        int r = row0 + ((i < 4) ? (ty * 4 + i) : (64 + ty * 4 + i - 4));
        if (r >= cnt) continue;
        #pragma unroll
        for (int jh = 0; jh < 2; jh++) {
            #pragma unroll
            for (int j = 0; j < 4; j++) {
                int c = col0 + tx * 4 + jh * 64 + j;
                g_eo[((size_t)e * EROWS + r) * CC + c] = acc[i][jh * 4 + j] + eb2[e * CC + c];
            }
        }
    }
}

// ---------------- combine + aux ----------------
__global__ void combine_kernel(float* __restrict__ out) {
    int t = blockIdx.x;
    int tid = threadIdx.x;
    int r0 = g_tokrow[t * 2], r1 = g_tokrow[t * 2 + 1];
    float g0 = g_tokgate[t * 2], g1 = g_tokgate[t * 2 + 1];
    const float* x2 = g_x2 + (size_t)t * CC;
    const float* e0 = g_eo + (size_t)r0 * CC;
    const float* e1 = g_eo + (size_t)r1 * CC;
    float* orow = out + (size_t)t * CC;
    for (int c = tid; c < CC; c += 128)
        orow[c] = x2[c] + g0 * e0[c] + g1 * e1[c];
}

__global__ void aux_kernel(float* __restrict__ out, int out_size) {
    if (threadIdx.x == 0 && blockIdx.x == 0) {
        float a = 0.0f;
        for (int e = 0; e < EE; e++)
            a += (g_count[e] / (float)TOK) * (g_Psum[e] / (float)TOK);
        a *= (float)EE;
        if (out_size > TOK * CC) out[TOK * CC] = a;
    }
}

// ---------------- launch ----------------
extern "C" void kernel_launch(void* const* d_in, const int* in_sizes, int n_in,
                              void* d_out, int out_size) {
    const float* x      = (const float*)d_in[0];
    const float* vision = (const float*)d_in[1];
    const float* ln1_g = (const float*)d_in[2];  const float* ln1_b = (const float*)d_in[3];
    const float* ln2_g = (const float*)d_in[4];  const float* ln2_b = (const float*)d_in[5];
    const float* ln3_g = (const float*)d_in[6];  const float* ln3_b = (const float*)d_in[7];
    const float* sa_wq = (const float*)d_in[8];  const float* sa_bq = (const float*)d_in[9];
    const float* sa_wk = (const float*)d_in[10]; const float* sa_bk = (const float*)d_in[11];
    const float* sa_wv = (const float*)d_in[12]; const float* sa_bv = (const float*)d_in[13];
    const float* sa_wo = (const float*)d_in[14]; const float* sa_bo = (const float*)d_in[15];
    const float* ca_wq = (const float*)d_in[16]; const float* ca_bq = (const float*)d_in[17];
    const float* ca_wk = (const float*)d_in[18]; const float* ca_bk = (const float*)d_in[19];
    const float* ca_wv = (const float*)d_in[20]; const float* ca_bv = (const float*)d_in[21];
    const float* ca_wo = (const float*)d_in[22]; const float* ca_bo = (const float*)d_in[23];
    const float* rw    = (const float*)d_in[24]; const float* rb    = (const float*)d_in[25];
    const float* ew1   = (const float*)d_in[26]; const float* eb1   = (const float*)d_in[27];
    const float* ew2   = (const float*)d_in[28]; const float* eb2   = (const float*)d_in[29];
    float* out = (float*)d_out;

    float *p_h, *p_q, *p_k, *p_v, *p_att, *p_x1, *p_x2;
    cudaGetSymbolAddress((void**)&p_h,  g_h);
    cudaGetSymbolAddress((void**)&p_q,  g_q);
    cudaGetSymbolAddress((void**)&p_k,  g_k);
    cudaGetSymbolAddress((void**)&p_v,  g_v);
    cudaGetSymbolAddress((void**)&p_att, g_att);
    cudaGetSymbolAddress((void**)&p_x1, g_x1);
    cudaGetSymbolAddress((void**)&p_x2, g_x2);

    const int flash_smem = FLASH_SMEM_FLOATS * (int)sizeof(float);   // 84,992 B
    cudaFuncSetAttribute(flash_kernel, cudaFuncAttributeMaxDynamicSharedMemorySize, flash_smem);

    dim3 gC(CC / 128, TOK / 128);            // 4 x 64
    dim3 gKVsa(2, TOK / 128);                // fused K+V, self
    dim3 gKVca(2, (BB * MV) / 128);          // fused K+V, cross (2304 = 18*128)
    dim3 gAtt(NN / 128, HH, BB);             // 16 x 8 x 4

    // --- block 1: pre-norm causal GQA self-attn + residual ---
    ln_kernel<<<TOK, 256>>>(x, ln1_g, ln1_b, p_h);
    gemm128<<<gC, 256>>>(p_h, sa_wq, sa_bq, nullptr, p_q, TOK, CC, CC);
    kvgemm128<<<gKVsa, 256>>>(p_h, sa_wk, sa_bk, sa_wv, sa_bv, p_k, p_v, TOK, CC);
    flash_kernel<<<gAtt, 256, flash_smem>>>(p_q, p_k, p_v, p_att, NN, 1);
    gemm128<<<gC, 256>>>(p_att, sa_wo, sa_bo, x, p_x1, TOK, CC, CC);

    // --- block 2: pre-norm cross-attn + residual ---
    ln_kernel<<<TOK, 256>>>(p_x1, ln2_g, ln2_b, p_h);
    gemm128<<<gC, 256>>>(p_h, ca_wq, ca_bq, nullptr, p_q, TOK, CC, CC);
    kvgemm128<<<gKVca, 256>>>(vision, ca_wk, ca_bk, ca_wv, ca_bv, p_k, p_v, BB * MV, CC);
    flash_kernel<<<gAtt, 256, flash_smem>>>(p_q, p_k, p_v, p_att, MV, 0);
    gemm128<<<gC, 256>>>(p_att, ca_wo, ca_bo, p_x1, p_x2, TOK, CC, CC);

    // --- block 3: pre-norm MoE + residual (sparse: only routed experts) ---
    ln_kernel<<<TOK, 256>>>(p_x2, ln3_g, ln3_b, p_h);
    zero_kernel<<<1, 32>>>();
    router_kernel<<<TOK / 256, 256>>>(rw, rb);
    egemm1_kernel<<<dim3(FF / 128, EROWS / 128, EE), 256>>>(ew1, eb1);
    egemm2_kernel<<<dim3(CC / 128, EROWS / 128, EE), 256>>>(ew2, eb2);
    combine_kernel<<<TOK, 128>>>(out);
    aux_kernel<<<1, 1>>>(out, out_size);
}